// round 7
// baseline (speedup 1.0000x reference)
#include <cuda_runtime.h>
#include <math.h>

#define BATCH   32
#define W_GRID  640
#define H_GRID  480
#define IMG_H   480
#define IMG_W   640
#define NPIX    (BATCH * W_GRID * H_GRID)   // 9,830,400
#define NGROUP  (NPIX / 4)                  // 2,457,600 4-pixel groups
#define P1_BLOCKS (148 * 4)                 // 592
#define P2_BLOCKS ((NGROUP + 255) / 256)    // 9600

// zero-initialized; g_max_bits reset by sample_kernel's last block each run
__device__ unsigned int g_max_bits;
__device__ unsigned int g_done;

__device__ __forceinline__ unsigned int float_to_ordered(float f) {
    unsigned int u = __float_as_uint(f);
    return (u & 0x80000000u) ? ~u : (u | 0x80000000u);
}
__device__ __forceinline__ float ordered_to_float(unsigned int u) {
    unsigned int b = (u & 0x80000000u) ? (u ^ 0x80000000u) : ~u;
    return __uint_as_float(b);
}
__device__ __forceinline__ float frcp_approx(float x) {
    float r;
    asm("rcp.approx.f32 %0, %1;" : "=f"(r) : "f"(x));
    return r;
}

// Per-block fold: threads 0..31 build M_b = Ki*T33*K (rows) + c_b = T[3,:3]*K into sM.
// Deterministic and identical across blocks.
__device__ __forceinline__ void build_sM(
    float (&sM)[BATCH][12],
    const float* __restrict__ T, const float* __restrict__ K)
{
    if (threadIdx.x < BATCH) {
        float a = K[0], b = K[1], c = K[2];
        float d = K[3], e = K[4], f = K[5];
        float g = K[6], h = K[7], i = K[8];
        float A  =  (e * i - f * h);
        float Bc = -(d * i - f * g);
        float C  =  (d * h - e * g);
        float det = a * A + b * Bc + c * C;
        float Ki[9];
        Ki[0] = __fdiv_rn(A, det);
        Ki[1] = __fdiv_rn(-(b * i - c * h), det);
        Ki[2] = __fdiv_rn((b * f - c * e), det);
        Ki[3] = __fdiv_rn(Bc, det);
        Ki[4] = __fdiv_rn((a * i - c * g), det);
        Ki[5] = __fdiv_rn(-(a * f - c * d), det);
        Ki[6] = __fdiv_rn(C, det);
        Ki[7] = __fdiv_rn(-(a * h - b * g), det);
        Ki[8] = __fdiv_rn((a * e - b * d), det);

        int bidx = threadIdx.x;
        const float* Tb = T + bidx * 16;
        float A2[9];
        #pragma unroll
        for (int k = 0; k < 3; k++)
            #pragma unroll
            for (int j = 0; j < 3; j++)
                A2[k * 3 + j] = fmaf(Tb[k * 4 + 0], K[0 * 3 + j],
                                fmaf(Tb[k * 4 + 1], K[1 * 3 + j],
                                     Tb[k * 4 + 2] * K[2 * 3 + j]));
        #pragma unroll
        for (int r = 0; r < 3; r++)
            #pragma unroll
            for (int j = 0; j < 3; j++)
                sM[bidx][r * 3 + j] = fmaf(Ki[r * 3 + 0], A2[0 * 3 + j],
                                      fmaf(Ki[r * 3 + 1], A2[1 * 3 + j],
                                           Ki[r * 3 + 2] * A2[2 * 3 + j]));
        #pragma unroll
        for (int j = 0; j < 3; j++)
            sM[bidx][9 + j] = fmaf(Tb[12], K[0 * 3 + j],
                               fmaf(Tb[13], K[1 * 3 + j],
                                    Tb[14] * K[2 * 3 + j]));
    }
}

// Pass 1: global max of uv over all pixels (4 px / iteration).
__global__ void __launch_bounds__(256, 5) uv_max_kernel(
    const float* __restrict__ depth,
    const float* __restrict__ T,
    const float* __restrict__ K)
{
    __shared__ float sM[BATCH][12];
    build_sM(sM, T, K);
    __syncthreads();

    float local_max = -INFINITY;
    int stride = gridDim.x * blockDim.x;
    for (int g = blockIdx.x * blockDim.x + threadIdx.x; g < NGROUP; g += stride) {
        int hj4 = (g % (H_GRID / 4)) * 4;
        int t   = g / (H_GRID / 4);
        int wi  = t % W_GRID;
        int b   = t / W_GRID;

        float4 d4 = *reinterpret_cast<const float4*>(
            depth + ((size_t)b * W_GRID + wi) * H_GRID + hj4);
        const float* Mb = sM[b];
        float u = (float)hj4, v = (float)wi;

        float e0 = fmaf(u, Mb[0], fmaf(v, Mb[3], Mb[6]));
        float e1 = fmaf(u, Mb[1], fmaf(v, Mb[4], Mb[7]));
        float e2 = fmaf(u, Mb[2], fmaf(v, Mb[5], Mb[8]));
        float c0 = Mb[9], c1 = Mb[10], c2 = Mb[11];

        float dv[4] = {d4.x, d4.y, d4.z, d4.w};
        #pragma unroll
        for (int k = 0; k < 4; k++) {
            float q0 = fmaf(dv[k], e0, c0);
            float q1 = fmaf(dv[k], e1, c1);
            float q2 = fmaf(dv[k], e2, c2);
            float rden = frcp_approx(q2 + 1e-4f);
            local_max = fmaxf(local_max, fmaxf(q0 * rden, q1 * rden));
            e0 += Mb[0]; e1 += Mb[1]; e2 += Mb[2];
        }
    }

    #pragma unroll
    for (int off = 16; off > 0; off >>= 1)
        local_max = fmaxf(local_max, __shfl_xor_sync(0xffffffffu, local_max, off));

    __shared__ float smax[8];
    int warp = threadIdx.x >> 5;
    int lane = threadIdx.x & 31;
    if (lane == 0) smax[warp] = local_max;
    __syncthreads();
    if (warp == 0) {
        float m = (lane < 8) ? smax[lane] : -INFINITY;
        #pragma unroll
        for (int off = 4; off > 0; off >>= 1)
            m = fmaxf(m, __shfl_xor_sync(0xffffffffu, m, off));
        if (lane == 0) atomicMax(&g_max_bits, float_to_ordered(m));
    }
}

// Pass 2: bilinear sample with integer-native address path. 4 px/thread.
__global__ void __launch_bounds__(256, 5) sample_kernel(
    const float* __restrict__ depth,
    const float* __restrict__ T,
    const float* __restrict__ K,
    const float* __restrict__ image,
    float* __restrict__ out)
{
    __shared__ float sM[BATCH][12];
    build_sM(sM, T, K);
    __syncthreads();

    int g = blockIdx.x * blockDim.x + threadIdx.x;
    if (g < NGROUP) {
        int hj4 = (g % (H_GRID / 4)) * 4;
        int t   = g / (H_GRID / 4);
        int wi  = t % W_GRID;
        int b   = t / W_GRID;

        float gmax = ordered_to_float(g_max_bits);
        float rg = __fdiv_rn(1.0f, gmax);
        float sx = (float)IMG_W * rg;
        float sy = (float)IMG_H * rg;

        float4 d4 = *reinterpret_cast<const float4*>(
            depth + ((size_t)b * W_GRID + wi) * H_GRID + hj4);
        const float* Mb = sM[b];
        float u = (float)hj4, v = (float)wi;

        float e0 = fmaf(u, Mb[0], fmaf(v, Mb[3], Mb[6]));
        float e1 = fmaf(u, Mb[1], fmaf(v, Mb[4], Mb[7]));
        float e2 = fmaf(u, Mb[2], fmaf(v, Mb[5], Mb[8]));
        float c0 = Mb[9], c1 = Mb[10], c2 = Mb[11];
        float m0 = Mb[0], m1 = Mb[1], m2 = Mb[2];

        const float* img_b = image + (size_t)b * 3 * IMG_H * IMG_W;
        float r[3][4];
        float dv[4] = {d4.x, d4.y, d4.z, d4.w};

        #pragma unroll
        for (int k = 0; k < 4; k++) {
            float q0 = fmaf(dv[k], e0, c0);
            float q1 = fmaf(dv[k], e1, c1);
            float q2 = fmaf(dv[k], e2, c2);
            e0 += m0; e1 += m1; e2 += m2;

            float rden = frcp_approx(q2 + 1e-4f);
            float x = fmaf(q0, rden * sx, -0.5f);
            float y = fmaf(q1, rden * sy, -0.5f);

            // integer-native floor / validity / clamp
            int ix = __float2int_rd(x);
            int iy = __float2int_rd(y);
            float wx = x - __int2float_rn(ix);
            float wy = y - __int2float_rn(iy);

            bool vx0 = (unsigned)ix       < (unsigned)IMG_W;
            bool vx1 = (unsigned)(ix + 1) < (unsigned)IMG_W;
            bool vy0 = (unsigned)iy       < (unsigned)IMG_H;
            bool vy1 = (unsigned)(iy + 1) < (unsigned)IMG_H;

            int xi0 = min(max(ix, 0),     IMG_W - 1);
            int xi1 = min(max(ix + 1, 0), IMG_W - 1);
            int yi0 = min(max(iy, 0),     IMG_H - 1);
            int yi1 = min(max(iy + 1, 0), IMG_H - 1);

            float wx0 = 1.0f - wx, wy0 = 1.0f - wy;
            float w00 = (vx0 && vy0) ? wx0 * wy0 : 0.0f;
            float w01 = (vx1 && vy0) ? wx  * wy0 : 0.0f;
            float w10 = (vx0 && vy1) ? wx0 * wy  : 0.0f;
            float w11 = (vx1 && vy1) ? wx  * wy  : 0.0f;

            int dx  = xi1 - xi0;
            int i00 = yi0 * IMG_W + xi0;
            int i01 = i00 + dx;
            int i10 = i00 + (yi1 - yi0) * IMG_W;
            int i11 = i10 + dx;

            #pragma unroll
            for (int c = 0; c < 3; c++) {
                const float* ch = img_b + (size_t)c * (IMG_H * IMG_W);
                r[c][k] = w00 * ch[i00] + w01 * ch[i01] + w10 * ch[i10] + w11 * ch[i11];
            }
        }

        size_t out_base = ((size_t)b * 3) * (size_t)(W_GRID * H_GRID)
                        + (size_t)wi * H_GRID + hj4;
        #pragma unroll
        for (int c = 0; c < 3; c++) {
            float4 o = make_float4(r[c][0], r[c][1], r[c][2], r[c][3]);
            *reinterpret_cast<float4*>(out + out_base + (size_t)c * (W_GRID * H_GRID)) = o;
        }
    }

    // last-block cleanup: reset g_max_bits for the next graph replay.
    // Every block read g_max_bits before incrementing g_done, so the reset
    // (performed by the final incrementer) races with nothing.
    __syncthreads();
    if (threadIdx.x == 0) {
        __threadfence();
        unsigned int prev = atomicAdd(&g_done, 1u);
        if (prev == (unsigned)(P2_BLOCKS - 1)) {
            g_max_bits = 0u;
            g_done = 0u;
            __threadfence();
        }
    }
}

extern "C" void kernel_launch(void* const* d_in, const int* in_sizes, int n_in,
                              void* d_out, int out_size) {
    const float* depth = (const float*)d_in[0];   // [32, 640, 480, 1]
    const float* T     = (const float*)d_in[1];   // [32, 4, 4]
    const float* image = (const float*)d_in[2];   // [32, 3, 480, 640]
    const float* K     = (const float*)d_in[3];   // [3, 3]
    float* out = (float*)d_out;                   // [32, 3, 640, 480]

    uv_max_kernel<<<P1_BLOCKS, 256>>>(depth, T, K);
    sample_kernel<<<P2_BLOCKS, 256>>>(depth, T, K, image, out);
}

// round 8
// speedup vs baseline: 1.2324x; 1.2324x over previous
#include <cuda_runtime.h>
#include <math.h>

#define BATCH   32
#define W_GRID  640
#define H_GRID  480
#define IMG_H   480
#define IMG_W   640
#define NPIX    (BATCH * W_GRID * H_GRID)   // 9,830,400
#define NGROUP  (NPIX / 4)                  // 2,457,600 4-pixel groups
#define P1_BLOCKS (148 * 4)                 // 592
#define P2_BLOCKS ((NGROUP + 255) / 256)    // 9600

// zero-initialized; g_max_bits reset by sample_kernel's last block each run
__device__ unsigned int g_max_bits;
__device__ unsigned int g_done;
__device__ float g_M[BATCH][12];            // written by uv_max block 0

__device__ __forceinline__ unsigned int float_to_ordered(float f) {
    unsigned int u = __float_as_uint(f);
    return (u & 0x80000000u) ? ~u : (u | 0x80000000u);
}
__device__ __forceinline__ float ordered_to_float(unsigned int u) {
    unsigned int b = (u & 0x80000000u) ? (u ^ 0x80000000u) : ~u;
    return __uint_as_float(b);
}
__device__ __forceinline__ float frcp_approx(float x) {
    float r;
    asm("rcp.approx.f32 %0, %1;" : "=f"(r) : "f"(x));
    return r;
}

// Pass 1: build folded matrices per block (cheap at 592 blocks); block 0 also
// publishes them to g_M for pass 2. Then global max of uv over all pixels.
__global__ void __launch_bounds__(256, 5) uv_max_kernel(
    const float* __restrict__ depth,
    const float* __restrict__ T,
    const float* __restrict__ K)
{
    __shared__ float sM[BATCH][12];

    if (threadIdx.x < BATCH) {
        float a = K[0], b = K[1], c = K[2];
        float d = K[3], e = K[4], f = K[5];
        float g = K[6], h = K[7], i = K[8];
        float A  =  (e * i - f * h);
        float Bc = -(d * i - f * g);
        float C  =  (d * h - e * g);
        float det = a * A + b * Bc + c * C;
        float Ki[9];
        Ki[0] = __fdiv_rn(A, det);
        Ki[1] = __fdiv_rn(-(b * i - c * h), det);
        Ki[2] = __fdiv_rn((b * f - c * e), det);
        Ki[3] = __fdiv_rn(Bc, det);
        Ki[4] = __fdiv_rn((a * i - c * g), det);
        Ki[5] = __fdiv_rn(-(a * f - c * d), det);
        Ki[6] = __fdiv_rn(C, det);
        Ki[7] = __fdiv_rn(-(a * h - b * g), det);
        Ki[8] = __fdiv_rn((a * e - b * d), det);

        int bidx = threadIdx.x;
        const float* Tb = T + bidx * 16;
        float A2[9];
        #pragma unroll
        for (int k = 0; k < 3; k++)
            #pragma unroll
            for (int j = 0; j < 3; j++)
                A2[k * 3 + j] = fmaf(Tb[k * 4 + 0], K[0 * 3 + j],
                                fmaf(Tb[k * 4 + 1], K[1 * 3 + j],
                                     Tb[k * 4 + 2] * K[2 * 3 + j]));
        float Mv[12];
        #pragma unroll
        for (int r = 0; r < 3; r++)
            #pragma unroll
            for (int j = 0; j < 3; j++)
                Mv[r * 3 + j] = fmaf(Ki[r * 3 + 0], A2[0 * 3 + j],
                                fmaf(Ki[r * 3 + 1], A2[1 * 3 + j],
                                     Ki[r * 3 + 2] * A2[2 * 3 + j]));
        #pragma unroll
        for (int j = 0; j < 3; j++)
            Mv[9 + j] = fmaf(Tb[12], K[0 * 3 + j],
                        fmaf(Tb[13], K[1 * 3 + j],
                             Tb[14] * K[2 * 3 + j]));
        #pragma unroll
        for (int j = 0; j < 12; j++) sM[bidx][j] = Mv[j];
        if (blockIdx.x == 0) {
            #pragma unroll
            for (int j = 0; j < 12; j++) g_M[bidx][j] = Mv[j];
        }
    }
    __syncthreads();

    float local_max = -INFINITY;
    int stride = gridDim.x * blockDim.x;
    for (int g = blockIdx.x * blockDim.x + threadIdx.x; g < NGROUP; g += stride) {
        int hj4 = (g % (H_GRID / 4)) * 4;
        int t   = g / (H_GRID / 4);
        int wi  = t % W_GRID;
        int b   = t / W_GRID;

        float4 d4 = *reinterpret_cast<const float4*>(
            depth + ((size_t)b * W_GRID + wi) * H_GRID + hj4);
        const float* Mb = sM[b];
        float u = (float)hj4, v = (float)wi;

        float e0 = fmaf(u, Mb[0], fmaf(v, Mb[3], Mb[6]));
        float e1 = fmaf(u, Mb[1], fmaf(v, Mb[4], Mb[7]));
        float e2 = fmaf(u, Mb[2], fmaf(v, Mb[5], Mb[8]));
        float c0 = Mb[9], c1 = Mb[10], c2 = Mb[11];

        float dv[4] = {d4.x, d4.y, d4.z, d4.w};
        #pragma unroll
        for (int k = 0; k < 4; k++) {
            float q0 = fmaf(dv[k], e0, c0);
            float q1 = fmaf(dv[k], e1, c1);
            float q2 = fmaf(dv[k], e2, c2);
            float rden = frcp_approx(q2 + 1e-4f);
            local_max = fmaxf(local_max, fmaxf(q0 * rden, q1 * rden));
            e0 += Mb[0]; e1 += Mb[1]; e2 += Mb[2];
        }
    }

    #pragma unroll
    for (int off = 16; off > 0; off >>= 1)
        local_max = fmaxf(local_max, __shfl_xor_sync(0xffffffffu, local_max, off));

    __shared__ float smax[8];
    int warp = threadIdx.x >> 5;
    int lane = threadIdx.x & 31;
    if (lane == 0) smax[warp] = local_max;
    __syncthreads();
    if (warp == 0) {
        float m = (lane < 8) ? smax[lane] : -INFINITY;
        #pragma unroll
        for (int off = 4; off > 0; off >>= 1)
            m = fmaxf(m, __shfl_xor_sync(0xffffffffu, m, off));
        if (lane == 0) atomicMax(&g_max_bits, float_to_ordered(m));
    }
}

// Pass 2: R5 structure (g_M from global, no shared build), integer address path.
__global__ void __launch_bounds__(256, 5) sample_kernel(
    const float* __restrict__ depth,
    const float* __restrict__ image,
    float* __restrict__ out)
{
    int g = blockIdx.x * blockDim.x + threadIdx.x;
    if (g < NGROUP) {
        int hj4 = (g % (H_GRID / 4)) * 4;
        int t   = g / (H_GRID / 4);
        int wi  = t % W_GRID;
        int b   = t / W_GRID;

        float gmax = ordered_to_float(g_max_bits);
        float rg = __fdiv_rn(1.0f, gmax);
        float sx = (float)IMG_W * rg;
        float sy = (float)IMG_H * rg;

        float4 d4 = *reinterpret_cast<const float4*>(
            depth + ((size_t)b * W_GRID + wi) * H_GRID + hj4);
        const float* Mb = g_M[b];
        float u = (float)hj4, v = (float)wi;

        float m0 = Mb[0], m1 = Mb[1], m2 = Mb[2];
        float e0 = fmaf(u, m0, fmaf(v, Mb[3], Mb[6]));
        float e1 = fmaf(u, m1, fmaf(v, Mb[4], Mb[7]));
        float e2 = fmaf(u, m2, fmaf(v, Mb[5], Mb[8]));
        float c0 = Mb[9], c1 = Mb[10], c2 = Mb[11];

        const float* img_b = image + (size_t)b * 3 * IMG_H * IMG_W;
        float r[3][4];
        float dv[4] = {d4.x, d4.y, d4.z, d4.w};

        #pragma unroll
        for (int k = 0; k < 4; k++) {
            float q0 = fmaf(dv[k], e0, c0);
            float q1 = fmaf(dv[k], e1, c1);
            float q2 = fmaf(dv[k], e2, c2);
            e0 += m0; e1 += m1; e2 += m2;

            float rden = frcp_approx(q2 + 1e-4f);
            float x = fmaf(q0, rden * sx, -0.5f);
            float y = fmaf(q1, rden * sy, -0.5f);

            int ix = __float2int_rd(x);
            int iy = __float2int_rd(y);
            float wx = x - __int2float_rn(ix);
            float wy = y - __int2float_rn(iy);

            bool vx0 = (unsigned)ix       < (unsigned)IMG_W;
            bool vx1 = (unsigned)(ix + 1) < (unsigned)IMG_W;
            bool vy0 = (unsigned)iy       < (unsigned)IMG_H;
            bool vy1 = (unsigned)(iy + 1) < (unsigned)IMG_H;

            int xi0 = min(max(ix, 0),     IMG_W - 1);
            int xi1 = min(max(ix + 1, 0), IMG_W - 1);
            int yi0 = min(max(iy, 0),     IMG_H - 1);
            int yi1 = min(max(iy + 1, 0), IMG_H - 1);

            float wx0 = 1.0f - wx, wy0 = 1.0f - wy;
            float w00 = (vx0 && vy0) ? wx0 * wy0 : 0.0f;
            float w01 = (vx1 && vy0) ? wx  * wy0 : 0.0f;
            float w10 = (vx0 && vy1) ? wx0 * wy  : 0.0f;
            float w11 = (vx1 && vy1) ? wx  * wy  : 0.0f;

            int dx  = xi1 - xi0;
            int i00 = yi0 * IMG_W + xi0;
            int i01 = i00 + dx;
            int i10 = i00 + (yi1 - yi0) * IMG_W;
            int i11 = i10 + dx;

            #pragma unroll
            for (int c = 0; c < 3; c++) {
                const float* ch = img_b + (size_t)c * (IMG_H * IMG_W);
                r[c][k] = w00 * ch[i00] + w01 * ch[i01] + w10 * ch[i10] + w11 * ch[i11];
            }
        }

        size_t out_base = ((size_t)b * 3) * (size_t)(W_GRID * H_GRID)
                        + (size_t)wi * H_GRID + hj4;
        #pragma unroll
        for (int c = 0; c < 3; c++) {
            float4 o = make_float4(r[c][0], r[c][1], r[c][2], r[c][3]);
            *reinterpret_cast<float4*>(out + out_base + (size_t)c * (W_GRID * H_GRID)) = o;
        }
    }

    // last-block cleanup: reset g_max_bits for the next graph replay.
    // __syncthreads ensures every thread of this block has already read
    // g_max_bits before thread 0 increments the arrival counter.
    __syncthreads();
    if (threadIdx.x == 0) {
        __threadfence();
        unsigned int prev = atomicAdd(&g_done, 1u);
        if (prev == (unsigned)(P2_BLOCKS - 1)) {
            g_max_bits = 0u;
            g_done = 0u;
            __threadfence();
        }
    }
}

extern "C" void kernel_launch(void* const* d_in, const int* in_sizes, int n_in,
                              void* d_out, int out_size) {
    const float* depth = (const float*)d_in[0];   // [32, 640, 480, 1]
    const float* T     = (const float*)d_in[1];   // [32, 4, 4]
    const float* image = (const float*)d_in[2];   // [32, 3, 480, 640]
    const float* K     = (const float*)d_in[3];   // [3, 3]
    float* out = (float*)d_out;                   // [32, 3, 640, 480]

    uv_max_kernel<<<P1_BLOCKS, 256>>>(depth, T, K);
    sample_kernel<<<P2_BLOCKS, 256>>>(depth, image, out);
}

// round 9
// speedup vs baseline: 1.2446x; 1.0100x over previous
#include <cuda_runtime.h>
#include <math.h>

#define BATCH   32
#define W_GRID  640
#define H_GRID  480
#define IMG_H   480
#define IMG_W   640
#define NPIX    (BATCH * W_GRID * H_GRID)   // 9,830,400
#define NGROUP  (NPIX / 4)                  // 2,457,600 4-pixel groups
#define P1_BLOCKS (148 * 4)                 // 592
#define P2_BLOCKS ((NGROUP + 255) / 256)    // 9600

// zero-initialized; g_max_bits reset by sample_kernel's last block each run
__device__ unsigned int g_max_bits;
__device__ unsigned int g_done;
__device__ float g_M[BATCH][12];            // written by uv_max block 0

__device__ __forceinline__ unsigned int float_to_ordered(float f) {
    unsigned int u = __float_as_uint(f);
    return (u & 0x80000000u) ? ~u : (u | 0x80000000u);
}
__device__ __forceinline__ float ordered_to_float(unsigned int u) {
    unsigned int b = (u & 0x80000000u) ? (u ^ 0x80000000u) : ~u;
    return __uint_as_float(b);
}
__device__ __forceinline__ float frcp_approx(float x) {
    float r;
    asm("rcp.approx.f32 %0, %1;" : "=f"(r) : "f"(x));
    return r;
}

// Pass 1: build folded matrices per block (cheap at 592 blocks); block 0 also
// publishes them to g_M for pass 2. Then global max of uv over all pixels.
__global__ void __launch_bounds__(256, 5) uv_max_kernel(
    const float* __restrict__ depth,
    const float* __restrict__ T,
    const float* __restrict__ K)
{
    __shared__ float sM[BATCH][12];

    if (threadIdx.x < BATCH) {
        float a = K[0], b = K[1], c = K[2];
        float d = K[3], e = K[4], f = K[5];
        float g = K[6], h = K[7], i = K[8];
        float A  =  (e * i - f * h);
        float Bc = -(d * i - f * g);
        float C  =  (d * h - e * g);
        float det = a * A + b * Bc + c * C;
        float Ki[9];
        Ki[0] = __fdiv_rn(A, det);
        Ki[1] = __fdiv_rn(-(b * i - c * h), det);
        Ki[2] = __fdiv_rn((b * f - c * e), det);
        Ki[3] = __fdiv_rn(Bc, det);
        Ki[4] = __fdiv_rn((a * i - c * g), det);
        Ki[5] = __fdiv_rn(-(a * f - c * d), det);
        Ki[6] = __fdiv_rn(C, det);
        Ki[7] = __fdiv_rn(-(a * h - b * g), det);
        Ki[8] = __fdiv_rn((a * e - b * d), det);

        int bidx = threadIdx.x;
        const float* Tb = T + bidx * 16;
        float A2[9];
        #pragma unroll
        for (int k = 0; k < 3; k++)
            #pragma unroll
            for (int j = 0; j < 3; j++)
                A2[k * 3 + j] = fmaf(Tb[k * 4 + 0], K[0 * 3 + j],
                                fmaf(Tb[k * 4 + 1], K[1 * 3 + j],
                                     Tb[k * 4 + 2] * K[2 * 3 + j]));
        float Mv[12];
        #pragma unroll
        for (int r = 0; r < 3; r++)
            #pragma unroll
            for (int j = 0; j < 3; j++)
                Mv[r * 3 + j] = fmaf(Ki[r * 3 + 0], A2[0 * 3 + j],
                                fmaf(Ki[r * 3 + 1], A2[1 * 3 + j],
                                     Ki[r * 3 + 2] * A2[2 * 3 + j]));
        #pragma unroll
        for (int j = 0; j < 3; j++)
            Mv[9 + j] = fmaf(Tb[12], K[0 * 3 + j],
                        fmaf(Tb[13], K[1 * 3 + j],
                             Tb[14] * K[2 * 3 + j]));
        #pragma unroll
        for (int j = 0; j < 12; j++) sM[bidx][j] = Mv[j];
        if (blockIdx.x == 0) {
            #pragma unroll
            for (int j = 0; j < 12; j++) g_M[bidx][j] = Mv[j];
        }
    }
    __syncthreads();

    float local_max = -INFINITY;
    int stride = gridDim.x * blockDim.x;
    for (int g = blockIdx.x * blockDim.x + threadIdx.x; g < NGROUP; g += stride) {
        int hj4 = (g % (H_GRID / 4)) * 4;
        int t   = g / (H_GRID / 4);
        int wi  = t % W_GRID;
        int b   = t / W_GRID;

        float4 d4 = *reinterpret_cast<const float4*>(
            depth + ((size_t)b * W_GRID + wi) * H_GRID + hj4);
        const float* Mb = sM[b];
        float u = (float)hj4, v = (float)wi;

        float e0 = fmaf(u, Mb[0], fmaf(v, Mb[3], Mb[6]));
        float e1 = fmaf(u, Mb[1], fmaf(v, Mb[4], Mb[7]));
        float e2 = fmaf(u, Mb[2], fmaf(v, Mb[5], Mb[8]));
        float c0 = Mb[9], c1 = Mb[10], c2 = Mb[11];

        float dv[4] = {d4.x, d4.y, d4.z, d4.w};
        #pragma unroll
        for (int k = 0; k < 4; k++) {
            float q0 = fmaf(dv[k], e0, c0);
            float q1 = fmaf(dv[k], e1, c1);
            float q2 = fmaf(dv[k], e2, c2);
            float rden = frcp_approx(q2 + 1e-4f);
            local_max = fmaxf(local_max, fmaxf(q0 * rden, q1 * rden));
            e0 += Mb[0]; e1 += Mb[1]; e2 += Mb[2];
        }
    }

    #pragma unroll
    for (int off = 16; off > 0; off >>= 1)
        local_max = fmaxf(local_max, __shfl_xor_sync(0xffffffffu, local_max, off));

    __shared__ float smax[8];
    int warp = threadIdx.x >> 5;
    int lane = threadIdx.x & 31;
    if (lane == 0) smax[warp] = local_max;
    __syncthreads();
    if (warp == 0) {
        float m = (lane < 8) ? smax[lane] : -INFINITY;
        #pragma unroll
        for (int off = 4; off > 0; off >>= 1)
            m = fmaxf(m, __shfl_xor_sync(0xffffffffu, m, off));
        if (lane == 0) atomicMax(&g_max_bits, float_to_ordered(m));
    }
}

// Pass 2: R5 float address path, g_M from global (register-hoisted), 4 px/thread.
__global__ void __launch_bounds__(256, 5) sample_kernel(
    const float* __restrict__ depth,
    const float* __restrict__ image,
    float* __restrict__ out)
{
    int g = blockIdx.x * blockDim.x + threadIdx.x;
    if (g < NGROUP) {
        int hj4 = (g % (H_GRID / 4)) * 4;
        int t   = g / (H_GRID / 4);
        int wi  = t % W_GRID;
        int b   = t / W_GRID;

        float gmax = ordered_to_float(g_max_bits);
        float rg = __fdiv_rn(1.0f, gmax);
        float sx = (float)IMG_W * rg;
        float sy = (float)IMG_H * rg;

        float4 d4 = *reinterpret_cast<const float4*>(
            depth + ((size_t)b * W_GRID + wi) * H_GRID + hj4);
        const float* Mb = g_M[b];
        float u = (float)hj4, v = (float)wi;

        float m0 = Mb[0], m1 = Mb[1], m2 = Mb[2];
        float e0 = fmaf(u, m0, fmaf(v, Mb[3], Mb[6]));
        float e1 = fmaf(u, m1, fmaf(v, Mb[4], Mb[7]));
        float e2 = fmaf(u, m2, fmaf(v, Mb[5], Mb[8]));
        float c0 = Mb[9], c1 = Mb[10], c2 = Mb[11];

        const float* img_b = image + (size_t)b * 3 * IMG_H * IMG_W;
        float r[3][4];
        float dv[4] = {d4.x, d4.y, d4.z, d4.w};

        #pragma unroll
        for (int k = 0; k < 4; k++) {
            float q0 = fmaf(dv[k], e0, c0);
            float q1 = fmaf(dv[k], e1, c1);
            float q2 = fmaf(dv[k], e2, c2);
            e0 += m0; e1 += m1; e2 += m2;

            float rden = frcp_approx(q2 + 1e-4f);
            float x = fmaf(q0, rden * sx, -0.5f);
            float y = fmaf(q1, rden * sy, -0.5f);

            float x0f = floorf(x);
            float y0f = floorf(y);
            float wx = x - x0f;
            float wy = y - y0f;
            float x1f = x0f + 1.0f;
            float y1f = y0f + 1.0f;

            float vx0 = (x0f >= 0.0f && x0f <= (float)(IMG_W - 1)) ? 1.0f : 0.0f;
            float vx1 = (x1f >= 0.0f && x1f <= (float)(IMG_W - 1)) ? 1.0f : 0.0f;
            float vy0 = (y0f >= 0.0f && y0f <= (float)(IMG_H - 1)) ? 1.0f : 0.0f;
            float vy1 = (y1f >= 0.0f && y1f <= (float)(IMG_H - 1)) ? 1.0f : 0.0f;

            int xi0 = (int)fminf(fmaxf(x0f, 0.0f), (float)(IMG_W - 1));
            int xi1 = (int)fminf(fmaxf(x1f, 0.0f), (float)(IMG_W - 1));
            int yi0 = (int)fminf(fmaxf(y0f, 0.0f), (float)(IMG_H - 1));
            int yi1 = (int)fminf(fmaxf(y1f, 0.0f), (float)(IMG_H - 1));

            float wx0 = 1.0f - wx, wy0 = 1.0f - wy;
            float w00 = wx0 * wy0 * (vx0 * vy0);
            float w01 = wx  * wy0 * (vx1 * vy0);
            float w10 = wx0 * wy  * (vx0 * vy1);
            float w11 = wx  * wy  * (vx1 * vy1);

            int dx  = xi1 - xi0;
            int i00 = yi0 * IMG_W + xi0;
            int i01 = i00 + dx;
            int i10 = i00 + (yi1 - yi0) * IMG_W;
            int i11 = i10 + dx;

            #pragma unroll
            for (int c = 0; c < 3; c++) {
                const float* ch = img_b + (size_t)c * (IMG_H * IMG_W);
                r[c][k] = w00 * ch[i00] + w01 * ch[i01] + w10 * ch[i10] + w11 * ch[i11];
            }
        }

        size_t out_base = ((size_t)b * 3) * (size_t)(W_GRID * H_GRID)
                        + (size_t)wi * H_GRID + hj4;
        #pragma unroll
        for (int c = 0; c < 3; c++) {
            float4 o = make_float4(r[c][0], r[c][1], r[c][2], r[c][3]);
            *reinterpret_cast<float4*>(out + out_base + (size_t)c * (W_GRID * H_GRID)) = o;
        }
    }

    // last-block cleanup: reset g_max_bits for the next graph replay.
    // __syncthreads ensures every thread of this block has already read
    // g_max_bits before thread 0 increments the arrival counter.
    __syncthreads();
    if (threadIdx.x == 0) {
        __threadfence();
        unsigned int prev = atomicAdd(&g_done, 1u);
        if (prev == (unsigned)(P2_BLOCKS - 1)) {
            g_max_bits = 0u;
            g_done = 0u;
            __threadfence();
        }
    }
}

extern "C" void kernel_launch(void* const* d_in, const int* in_sizes, int n_in,
                              void* d_out, int out_size) {
    const float* depth = (const float*)d_in[0];   // [32, 640, 480, 1]
    const float* T     = (const float*)d_in[1];   // [32, 4, 4]
    const float* image = (const float*)d_in[2];   // [32, 3, 480, 640]
    const float* K     = (const float*)d_in[3];   // [3, 3]
    float* out = (float*)d_out;                   // [32, 3, 640, 480]

    uv_max_kernel<<<P1_BLOCKS, 256>>>(depth, T, K);
    sample_kernel<<<P2_BLOCKS, 256>>>(depth, image, out);
}

// round 11
// speedup vs baseline: 1.2903x; 1.0367x over previous
#include <cuda_runtime.h>
#include <math.h>

#define BATCH   32
#define W_GRID  640
#define H_GRID  480
#define IMG_H   480
#define IMG_W   640
#define NPIX    (BATCH * W_GRID * H_GRID)   // 9,830,400
#define NGROUP  (NPIX / 4)                  // 2,457,600 4-pixel groups
#define P1_BLOCKS (148 * 8)                 // 1184
#define P2_BLOCKS ((NGROUP + 255) / 256)    // 9600

// zero-initialized; g_max_bits reset by sample_kernel's last block each run
__device__ unsigned int g_max_bits;
__device__ unsigned int g_done;
__device__ float g_M[BATCH][12];            // written by uv_max block 0

__device__ __forceinline__ unsigned int float_to_ordered(float f) {
    unsigned int u = __float_as_uint(f);
    return (u & 0x80000000u) ? ~u : (u | 0x80000000u);
}
__device__ __forceinline__ float ordered_to_float(unsigned int u) {
    unsigned int b = (u & 0x80000000u) ? (u ^ 0x80000000u) : ~u;
    return __uint_as_float(b);
}
__device__ __forceinline__ float frcp_approx(float x) {
    float r;
    asm("rcp.approx.f32 %0, %1;" : "=f"(r) : "f"(x));
    return r;
}

// Pass 1: build folded matrices per block; block 0 also publishes g_M for pass 2.
// Then global max of uv over all pixels.
__global__ void __launch_bounds__(256, 5) uv_max_kernel(
    const float* __restrict__ depth,
    const float* __restrict__ T,
    const float* __restrict__ K)
{
    __shared__ float sM[BATCH][12];

    if (threadIdx.x < BATCH) {
        float a = K[0], b = K[1], c = K[2];
        float d = K[3], e = K[4], f = K[5];
        float g = K[6], h = K[7], i = K[8];
        float A  =  (e * i - f * h);
        float Bc = -(d * i - f * g);
        float C  =  (d * h - e * g);
        float det = a * A + b * Bc + c * C;
        float Ki[9];
        Ki[0] = __fdiv_rn(A, det);
        Ki[1] = __fdiv_rn(-(b * i - c * h), det);
        Ki[2] = __fdiv_rn((b * f - c * e), det);
        Ki[3] = __fdiv_rn(Bc, det);
        Ki[4] = __fdiv_rn((a * i - c * g), det);
        Ki[5] = __fdiv_rn(-(a * f - c * d), det);
        Ki[6] = __fdiv_rn(C, det);
        Ki[7] = __fdiv_rn(-(a * h - b * g), det);
        Ki[8] = __fdiv_rn((a * e - b * d), det);

        int bidx = threadIdx.x;
        const float* Tb = T + bidx * 16;
        float A2[9];
        #pragma unroll
        for (int k = 0; k < 3; k++)
            #pragma unroll
            for (int j = 0; j < 3; j++)
                A2[k * 3 + j] = fmaf(Tb[k * 4 + 0], K[0 * 3 + j],
                                fmaf(Tb[k * 4 + 1], K[1 * 3 + j],
                                     Tb[k * 4 + 2] * K[2 * 3 + j]));
        float Mv[12];
        #pragma unroll
        for (int r = 0; r < 3; r++)
            #pragma unroll
            for (int j = 0; j < 3; j++)
                Mv[r * 3 + j] = fmaf(Ki[r * 3 + 0], A2[0 * 3 + j],
                                fmaf(Ki[r * 3 + 1], A2[1 * 3 + j],
                                     Ki[r * 3 + 2] * A2[2 * 3 + j]));
        #pragma unroll
        for (int j = 0; j < 3; j++)
            Mv[9 + j] = fmaf(Tb[12], K[0 * 3 + j],
                        fmaf(Tb[13], K[1 * 3 + j],
                             Tb[14] * K[2 * 3 + j]));
        #pragma unroll
        for (int j = 0; j < 12; j++) sM[bidx][j] = Mv[j];
        if (blockIdx.x == 0) {
            #pragma unroll
            for (int j = 0; j < 12; j++) g_M[bidx][j] = Mv[j];
        }
    }
    __syncthreads();

    float local_max = -INFINITY;
    int stride = gridDim.x * blockDim.x;
    for (int g = blockIdx.x * blockDim.x + threadIdx.x; g < NGROUP; g += stride) {
        int hj4 = (g % (H_GRID / 4)) * 4;
        int t   = g / (H_GRID / 4);
        int wi  = t % W_GRID;
        int b   = t / W_GRID;

        float4 d4 = *reinterpret_cast<const float4*>(
            depth + ((size_t)b * W_GRID + wi) * H_GRID + hj4);
        const float* Mb = sM[b];
        float u = (float)hj4, v = (float)wi;

        float e0 = fmaf(u, Mb[0], fmaf(v, Mb[3], Mb[6]));
        float e1 = fmaf(u, Mb[1], fmaf(v, Mb[4], Mb[7]));
        float e2 = fmaf(u, Mb[2], fmaf(v, Mb[5], Mb[8]));
        float c0 = Mb[9], c1 = Mb[10], c2 = Mb[11];

        float dv[4] = {d4.x, d4.y, d4.z, d4.w};
        #pragma unroll
        for (int k = 0; k < 4; k++) {
            float q0 = fmaf(dv[k], e0, c0);
            float q1 = fmaf(dv[k], e1, c1);
            float q2 = fmaf(dv[k], e2, c2);
            float rden = frcp_approx(q2 + 1e-4f);
            local_max = fmaxf(local_max, fmaxf(q0 * rden, q1 * rden));
            e0 += Mb[0]; e1 += Mb[1]; e2 += Mb[2];
        }
    }

    #pragma unroll
    for (int off = 16; off > 0; off >>= 1)
        local_max = fmaxf(local_max, __shfl_xor_sync(0xffffffffu, local_max, off));

    __shared__ float smax[8];
    int warp = threadIdx.x >> 5;
    int lane = threadIdx.x & 31;
    if (lane == 0) smax[warp] = local_max;
    __syncthreads();
    if (warp == 0) {
        float m = (lane < 8) ? smax[lane] : -INFINITY;
        #pragma unroll
        for (int off = 4; off > 0; off >>= 1)
            m = fmaxf(m, __shfl_xor_sync(0xffffffffu, m, off));
        if (lane == 0) atomicMax(&g_max_bits, float_to_ordered(m));
    }
}

// Pass 2: float address path, g_M from global (register-hoisted), 4 px/thread.
__global__ void __launch_bounds__(256, 6) sample_kernel(
    const float* __restrict__ depth,
    const float* __restrict__ image,
    float* __restrict__ out)
{
    int g = blockIdx.x * blockDim.x + threadIdx.x;
    if (g < NGROUP) {
        int hj4 = (g % (H_GRID / 4)) * 4;
        int t   = g / (H_GRID / 4);
        int wi  = t % W_GRID;
        int b   = t / W_GRID;

        float gmax = ordered_to_float(g_max_bits);
        float rg = frcp_approx(gmax);
        float sx = (float)IMG_W * rg;
        float sy = (float)IMG_H * rg;

        float4 d4 = *reinterpret_cast<const float4*>(
            depth + ((size_t)b * W_GRID + wi) * H_GRID + hj4);
        const float* Mb = g_M[b];
        float u = (float)hj4, v = (float)wi;

        float m0 = Mb[0], m1 = Mb[1], m2 = Mb[2];
        float e0 = fmaf(u, m0, fmaf(v, Mb[3], Mb[6]));
        float e1 = fmaf(u, m1, fmaf(v, Mb[4], Mb[7]));
        float e2 = fmaf(u, m2, fmaf(v, Mb[5], Mb[8]));
        float c0 = Mb[9], c1 = Mb[10], c2 = Mb[11];

        const float* img_b = image + (size_t)b * 3 * IMG_H * IMG_W;
        float r[3][4];
        float dv[4] = {d4.x, d4.y, d4.z, d4.w};

        #pragma unroll
        for (int k = 0; k < 4; k++) {
            float q0 = fmaf(dv[k], e0, c0);
            float q1 = fmaf(dv[k], e1, c1);
            float q2 = fmaf(dv[k], e2, c2);
            e0 += m0; e1 += m1; e2 += m2;

            float rden = frcp_approx(q2 + 1e-4f);
            float x = fmaf(q0, rden * sx, -0.5f);
            float y = fmaf(q1, rden * sy, -0.5f);

            float x0f = floorf(x);
            float y0f = floorf(y);
            float wx = x - x0f;
            float wy = y - y0f;
            float x1f = x0f + 1.0f;
            float y1f = y0f + 1.0f;

            float vx0 = (x0f >= 0.0f && x0f <= (float)(IMG_W - 1)) ? 1.0f : 0.0f;
            float vx1 = (x1f >= 0.0f && x1f <= (float)(IMG_W - 1)) ? 1.0f : 0.0f;
            float vy0 = (y0f >= 0.0f && y0f <= (float)(IMG_H - 1)) ? 1.0f : 0.0f;
            float vy1 = (y1f >= 0.0f && y1f <= (float)(IMG_H - 1)) ? 1.0f : 0.0f;

            int xi0 = (int)fminf(fmaxf(x0f, 0.0f), (float)(IMG_W - 1));
            int xi1 = (int)fminf(fmaxf(x1f, 0.0f), (float)(IMG_W - 1));
            int yi0 = (int)fminf(fmaxf(y0f, 0.0f), (float)(IMG_H - 1));
            int yi1 = (int)fminf(fmaxf(y1f, 0.0f), (float)(IMG_H - 1));

            float wx0 = 1.0f - wx, wy0 = 1.0f - wy;
            float w00 = wx0 * wy0 * (vx0 * vy0);
            float w01 = wx  * wy0 * (vx1 * vy0);
            float w10 = wx0 * wy  * (vx0 * vy1);
            float w11 = wx  * wy  * (vx1 * vy1);

            int dx  = xi1 - xi0;
            int i00 = yi0 * IMG_W + xi0;
            int i01 = i00 + dx;
            int i10 = i00 + (yi1 - yi0) * IMG_W;
            int i11 = i10 + dx;

            #pragma unroll
            for (int c = 0; c < 3; c++) {
                const float* ch = img_b + (size_t)c * (IMG_H * IMG_W);
                r[c][k] = w00 * ch[i00] + w01 * ch[i01] + w10 * ch[i10] + w11 * ch[i11];
            }
        }

        size_t out_base = ((size_t)b * 3) * (size_t)(W_GRID * H_GRID)
                        + (size_t)wi * H_GRID + hj4;
        #pragma unroll
        for (int c = 0; c < 3; c++) {
            float4 o = make_float4(r[c][0], r[c][1], r[c][2], r[c][3]);
            *reinterpret_cast<float4*>(out + out_base + (size_t)c * (W_GRID * H_GRID)) = o;
        }
    }

    // last-block cleanup: reset g_max_bits for the next graph replay.
    __syncthreads();
    if (threadIdx.x == 0) {
        __threadfence();
        unsigned int prev = atomicAdd(&g_done, 1u);
        if (prev == (unsigned)(P2_BLOCKS - 1)) {
            g_max_bits = 0u;
            g_done = 0u;
            __threadfence();
        }
    }
}

extern "C" void kernel_launch(void* const* d_in, const int* in_sizes, int n_in,
                              void* d_out, int out_size) {
    const float* depth = (const float*)d_in[0];   // [32, 640, 480, 1]
    const float* T     = (const float*)d_in[1];   // [32, 4, 4]
    const float* image = (const float*)d_in[2];   // [32, 3, 480, 640]
    const float* K     = (const float*)d_in[3];   // [3, 3]
    float* out = (float*)d_out;                   // [32, 3, 640, 480]

    uv_max_kernel<<<P1_BLOCKS, 256>>>(depth, T, K);
    sample_kernel<<<P2_BLOCKS, 256>>>(depth, image, out);
}

// round 12
// speedup vs baseline: 1.2910x; 1.0005x over previous
#include <cuda_runtime.h>
#include <math.h>

#define BATCH   32
#define W_GRID  640
#define H_GRID  480
#define IMG_H   480
#define IMG_W   640
#define NPIX    (BATCH * W_GRID * H_GRID)   // 9,830,400
#define NGROUP  (NPIX / 4)                  // 2,457,600 4-pixel groups
#define P1_BLOCKS (148 * 8)                 // 1184
#define P2_BLOCKS ((NGROUP + 255) / 256)    // 9600

// zero-initialized; g_max_bits reset by sample_kernel's last block each run
__device__ unsigned int g_max_bits;
__device__ unsigned int g_done;
__device__ float g_M[BATCH][12];            // written by uv_max block 0

__device__ __forceinline__ unsigned int float_to_ordered(float f) {
    unsigned int u = __float_as_uint(f);
    return (u & 0x80000000u) ? ~u : (u | 0x80000000u);
}
__device__ __forceinline__ float ordered_to_float(unsigned int u) {
    unsigned int b = (u & 0x80000000u) ? (u ^ 0x80000000u) : ~u;
    return __uint_as_float(b);
}
__device__ __forceinline__ float frcp_approx(float x) {
    float r;
    asm("rcp.approx.f32 %0, %1;" : "=f"(r) : "f"(x));
    return r;
}

// Fraction-pair running max: current max is qm/dm. Candidate q/den wins iff
// (q*dm - qm*den) * (den*dm) > 0  — no division, no divergence.
__device__ __forceinline__ void frac_max_update(float& qm, float& dm, float q, float den) {
    float s   = den * dm;
    float cmp = fmaf(-qm, den, q * dm);
    if (cmp * s > 0.0f) { qm = q; dm = den; }
}

// Pass 1: build folded matrices per block; block 0 also publishes g_M for pass 2.
// Then division-free global max of uv over all pixels.
__global__ void __launch_bounds__(256, 5) uv_max_kernel(
    const float* __restrict__ depth,
    const float* __restrict__ T,
    const float* __restrict__ K)
{
    __shared__ float sM[BATCH][12];

    if (threadIdx.x < BATCH) {
        float a = K[0], b = K[1], c = K[2];
        float d = K[3], e = K[4], f = K[5];
        float g = K[6], h = K[7], i = K[8];
        float A  =  (e * i - f * h);
        float Bc = -(d * i - f * g);
        float C  =  (d * h - e * g);
        float det = a * A + b * Bc + c * C;
        float Ki[9];
        Ki[0] = __fdiv_rn(A, det);
        Ki[1] = __fdiv_rn(-(b * i - c * h), det);
        Ki[2] = __fdiv_rn((b * f - c * e), det);
        Ki[3] = __fdiv_rn(Bc, det);
        Ki[4] = __fdiv_rn((a * i - c * g), det);
        Ki[5] = __fdiv_rn(-(a * f - c * d), det);
        Ki[6] = __fdiv_rn(C, det);
        Ki[7] = __fdiv_rn(-(a * h - b * g), det);
        Ki[8] = __fdiv_rn((a * e - b * d), det);

        int bidx = threadIdx.x;
        const float* Tb = T + bidx * 16;
        float A2[9];
        #pragma unroll
        for (int k = 0; k < 3; k++)
            #pragma unroll
            for (int j = 0; j < 3; j++)
                A2[k * 3 + j] = fmaf(Tb[k * 4 + 0], K[0 * 3 + j],
                                fmaf(Tb[k * 4 + 1], K[1 * 3 + j],
                                     Tb[k * 4 + 2] * K[2 * 3 + j]));
        float Mv[12];
        #pragma unroll
        for (int r = 0; r < 3; r++)
            #pragma unroll
            for (int j = 0; j < 3; j++)
                Mv[r * 3 + j] = fmaf(Ki[r * 3 + 0], A2[0 * 3 + j],
                                fmaf(Ki[r * 3 + 1], A2[1 * 3 + j],
                                     Ki[r * 3 + 2] * A2[2 * 3 + j]));
        #pragma unroll
        for (int j = 0; j < 3; j++)
            Mv[9 + j] = fmaf(Tb[12], K[0 * 3 + j],
                        fmaf(Tb[13], K[1 * 3 + j],
                             Tb[14] * K[2 * 3 + j]));
        #pragma unroll
        for (int j = 0; j < 12; j++) sM[bidx][j] = Mv[j];
        if (blockIdx.x == 0) {
            #pragma unroll
            for (int j = 0; j < 12; j++) g_M[bidx][j] = Mv[j];
        }
    }
    __syncthreads();

    // running max as fraction (qm/dm); init = -1e30 (safe lower bound for this data)
    float qm = -1e30f, dm = 1.0f;

    int stride = gridDim.x * blockDim.x;
    for (int g = blockIdx.x * blockDim.x + threadIdx.x; g < NGROUP; g += stride) {
        int hj4 = (g % (H_GRID / 4)) * 4;
        int t   = g / (H_GRID / 4);
        int wi  = t % W_GRID;
        int b   = t / W_GRID;

        float4 d4 = *reinterpret_cast<const float4*>(
            depth + ((size_t)b * W_GRID + wi) * H_GRID + hj4);
        const float* Mb = sM[b];
        float u = (float)hj4, v = (float)wi;

        float e0 = fmaf(u, Mb[0], fmaf(v, Mb[3], Mb[6]));
        float e1 = fmaf(u, Mb[1], fmaf(v, Mb[4], Mb[7]));
        float e2 = fmaf(u, Mb[2], fmaf(v, Mb[5], Mb[8]));
        float c0 = Mb[9], c1 = Mb[10], c2 = Mb[11];

        float dv[4] = {d4.x, d4.y, d4.z, d4.w};
        #pragma unroll
        for (int k = 0; k < 4; k++) {
            float q0 = fmaf(dv[k], e0, c0);
            float q1 = fmaf(dv[k], e1, c1);
            float q2 = fmaf(dv[k], e2, c2);
            float den = q2 + 1e-4f;
            frac_max_update(qm, dm, q0, den);
            frac_max_update(qm, dm, q1, den);
            e0 += Mb[0]; e1 += Mb[1]; e2 += Mb[2];
        }
    }

    // one IEEE divide per thread, then standard float reduction
    float local_max = __fdiv_rn(qm, dm);

    #pragma unroll
    for (int off = 16; off > 0; off >>= 1)
        local_max = fmaxf(local_max, __shfl_xor_sync(0xffffffffu, local_max, off));

    __shared__ float smax[8];
    int warp = threadIdx.x >> 5;
    int lane = threadIdx.x & 31;
    if (lane == 0) smax[warp] = local_max;
    __syncthreads();
    if (warp == 0) {
        float m = (lane < 8) ? smax[lane] : -INFINITY;
        #pragma unroll
        for (int off = 4; off > 0; off >>= 1)
            m = fmaxf(m, __shfl_xor_sync(0xffffffffu, m, off));
        if (lane == 0) atomicMax(&g_max_bits, float_to_ordered(m));
    }
}

// Pass 2: float address path, g_M from global (register-hoisted), 4 px/thread.
__global__ void __launch_bounds__(256, 6) sample_kernel(
    const float* __restrict__ depth,
    const float* __restrict__ image,
    float* __restrict__ out)
{
    int g = blockIdx.x * blockDim.x + threadIdx.x;
    if (g < NGROUP) {
        int hj4 = (g % (H_GRID / 4)) * 4;
        int t   = g / (H_GRID / 4);
        int wi  = t % W_GRID;
        int b   = t / W_GRID;

        float gmax = ordered_to_float(g_max_bits);
        float rg = frcp_approx(gmax);
        float sx = (float)IMG_W * rg;
        float sy = (float)IMG_H * rg;

        float4 d4 = *reinterpret_cast<const float4*>(
            depth + ((size_t)b * W_GRID + wi) * H_GRID + hj4);
        const float* Mb = g_M[b];
        float u = (float)hj4, v = (float)wi;

        float m0 = Mb[0], m1 = Mb[1], m2 = Mb[2];
        float e0 = fmaf(u, m0, fmaf(v, Mb[3], Mb[6]));
        float e1 = fmaf(u, m1, fmaf(v, Mb[4], Mb[7]));
        float e2 = fmaf(u, m2, fmaf(v, Mb[5], Mb[8]));
        float c0 = Mb[9], c1 = Mb[10], c2 = Mb[11];

        const float* img_b = image + (size_t)b * 3 * IMG_H * IMG_W;
        float r[3][4];
        float dv[4] = {d4.x, d4.y, d4.z, d4.w};

        #pragma unroll
        for (int k = 0; k < 4; k++) {
            float q0 = fmaf(dv[k], e0, c0);
            float q1 = fmaf(dv[k], e1, c1);
            float q2 = fmaf(dv[k], e2, c2);
            e0 += m0; e1 += m1; e2 += m2;

            float rden = frcp_approx(q2 + 1e-4f);
            float x = fmaf(q0, rden * sx, -0.5f);
            float y = fmaf(q1, rden * sy, -0.5f);

            float x0f = floorf(x);
            float y0f = floorf(y);
            float wx = x - x0f;
            float wy = y - y0f;
            float x1f = x0f + 1.0f;
            float y1f = y0f + 1.0f;

            float vx0 = (x0f >= 0.0f && x0f <= (float)(IMG_W - 1)) ? 1.0f : 0.0f;
            float vx1 = (x1f >= 0.0f && x1f <= (float)(IMG_W - 1)) ? 1.0f : 0.0f;
            float vy0 = (y0f >= 0.0f && y0f <= (float)(IMG_H - 1)) ? 1.0f : 0.0f;
            float vy1 = (y1f >= 0.0f && y1f <= (float)(IMG_H - 1)) ? 1.0f : 0.0f;

            int xi0 = (int)fminf(fmaxf(x0f, 0.0f), (float)(IMG_W - 1));
            int xi1 = (int)fminf(fmaxf(x1f, 0.0f), (float)(IMG_W - 1));
            int yi0 = (int)fminf(fmaxf(y0f, 0.0f), (float)(IMG_H - 1));
            int yi1 = (int)fminf(fmaxf(y1f, 0.0f), (float)(IMG_H - 1));

            float wx0 = 1.0f - wx, wy0 = 1.0f - wy;
            float w00 = wx0 * wy0 * (vx0 * vy0);
            float w01 = wx  * wy0 * (vx1 * vy0);
            float w10 = wx0 * wy  * (vx0 * vy1);
            float w11 = wx  * wy  * (vx1 * vy1);

            int dx  = xi1 - xi0;
            int i00 = yi0 * IMG_W + xi0;
            int i01 = i00 + dx;
            int i10 = i00 + (yi1 - yi0) * IMG_W;
            int i11 = i10 + dx;

            #pragma unroll
            for (int c = 0; c < 3; c++) {
                const float* ch = img_b + (size_t)c * (IMG_H * IMG_W);
                r[c][k] = w00 * ch[i00] + w01 * ch[i01] + w10 * ch[i10] + w11 * ch[i11];
            }
        }

        size_t out_base = ((size_t)b * 3) * (size_t)(W_GRID * H_GRID)
                        + (size_t)wi * H_GRID + hj4;
        #pragma unroll
        for (int c = 0; c < 3; c++) {
            float4 o = make_float4(r[c][0], r[c][1], r[c][2], r[c][3]);
            *reinterpret_cast<float4*>(out + out_base + (size_t)c * (W_GRID * H_GRID)) = o;
        }
    }

    // last-block cleanup: reset g_max_bits for the next graph replay.
    __syncthreads();
    if (threadIdx.x == 0) {
        __threadfence();
        unsigned int prev = atomicAdd(&g_done, 1u);
        if (prev == (unsigned)(P2_BLOCKS - 1)) {
            g_max_bits = 0u;
            g_done = 0u;
            __threadfence();
        }
    }
}

extern "C" void kernel_launch(void* const* d_in, const int* in_sizes, int n_in,
                              void* d_out, int out_size) {
    const float* depth = (const float*)d_in[0];   // [32, 640, 480, 1]
    const float* T     = (const float*)d_in[1];   // [32, 4, 4]
    const float* image = (const float*)d_in[2];   // [32, 3, 480, 640]
    const float* K     = (const float*)d_in[3];   // [3, 3]
    float* out = (float*)d_out;                   // [32, 3, 640, 480]

    uv_max_kernel<<<P1_BLOCKS, 256>>>(depth, T, K);
    sample_kernel<<<P2_BLOCKS, 256>>>(depth, image, out);
}

// round 14
// speedup vs baseline: 1.4439x; 1.1185x over previous
#include <cuda_runtime.h>
#include <math.h>

#define BATCH   32
#define W_GRID  640
#define H_GRID  480
#define IMG_H   480
#define IMG_W   640
#define NPIX    (BATCH * W_GRID * H_GRID)   // 9,830,400
#define NGROUP  (NPIX / 4)                  // 2,457,600 4-pixel groups
#define P1_BLOCKS (148 * 8)                 // 1184
#define P2_BLOCKS ((NGROUP + 255) / 256)    // 9600

// zero-initialized; g_max_bits reset by sample_kernel's last block each run
__device__ unsigned int g_max_bits;
__device__ unsigned int g_done;
__device__ float g_M[BATCH][12];            // written by uv_max block 0

__device__ __forceinline__ unsigned int float_to_ordered(float f) {
    unsigned int u = __float_as_uint(f);
    return (u & 0x80000000u) ? ~u : (u | 0x80000000u);
}
__device__ __forceinline__ float ordered_to_float(unsigned int u) {
    unsigned int b = (u & 0x80000000u) ? (u ^ 0x80000000u) : ~u;
    return __uint_as_float(b);
}
__device__ __forceinline__ float frcp_approx(float x) {
    float r;
    asm("rcp.approx.f32 %0, %1;" : "=f"(r) : "f"(x));
    return r;
}

// Fraction-pair running max: current max is qm/dm. Candidate q/den wins iff
// (q*dm - qm*den) * (den*dm) > 0  — no division, no divergence.
__device__ __forceinline__ void frac_max_update(float& qm, float& dm, float q, float den) {
    float s   = den * dm;
    float cmp = fmaf(-qm, den, q * dm);
    if (cmp * s > 0.0f) { qm = q; dm = den; }
}

// Pass 1: build folded matrices per block; block 0 also publishes g_M for pass 2.
// Then division-free global max of uv over all pixels.
__global__ void __launch_bounds__(256, 5) uv_max_kernel(
    const float* __restrict__ depth,
    const float* __restrict__ T,
    const float* __restrict__ K)
{
    __shared__ float sM[BATCH][12];

    if (threadIdx.x < BATCH) {
        float a = K[0], b = K[1], c = K[2];
        float d = K[3], e = K[4], f = K[5];
        float g = K[6], h = K[7], i = K[8];
        float A  =  (e * i - f * h);
        float Bc = -(d * i - f * g);
        float C  =  (d * h - e * g);
        float det = a * A + b * Bc + c * C;
        float Ki[9];
        Ki[0] = __fdiv_rn(A, det);
        Ki[1] = __fdiv_rn(-(b * i - c * h), det);
        Ki[2] = __fdiv_rn((b * f - c * e), det);
        Ki[3] = __fdiv_rn(Bc, det);
        Ki[4] = __fdiv_rn((a * i - c * g), det);
        Ki[5] = __fdiv_rn(-(a * f - c * d), det);
        Ki[6] = __fdiv_rn(C, det);
        Ki[7] = __fdiv_rn(-(a * h - b * g), det);
        Ki[8] = __fdiv_rn((a * e - b * d), det);

        int bidx = threadIdx.x;
        const float* Tb = T + bidx * 16;
        float A2[9];
        #pragma unroll
        for (int k = 0; k < 3; k++)
            #pragma unroll
            for (int j = 0; j < 3; j++)
                A2[k * 3 + j] = fmaf(Tb[k * 4 + 0], K[0 * 3 + j],
                                fmaf(Tb[k * 4 + 1], K[1 * 3 + j],
                                     Tb[k * 4 + 2] * K[2 * 3 + j]));
        float Mv[12];
        #pragma unroll
        for (int r = 0; r < 3; r++)
            #pragma unroll
            for (int j = 0; j < 3; j++)
                Mv[r * 3 + j] = fmaf(Ki[r * 3 + 0], A2[0 * 3 + j],
                                fmaf(Ki[r * 3 + 1], A2[1 * 3 + j],
                                     Ki[r * 3 + 2] * A2[2 * 3 + j]));
        #pragma unroll
        for (int j = 0; j < 3; j++)
            Mv[9 + j] = fmaf(Tb[12], K[0 * 3 + j],
                        fmaf(Tb[13], K[1 * 3 + j],
                             Tb[14] * K[2 * 3 + j]));
        #pragma unroll
        for (int j = 0; j < 12; j++) sM[bidx][j] = Mv[j];
        if (blockIdx.x == 0) {
            #pragma unroll
            for (int j = 0; j < 12; j++) g_M[bidx][j] = Mv[j];
        }
    }
    __syncthreads();

    float qm = -1e30f, dm = 1.0f;

    int stride = gridDim.x * blockDim.x;
    for (int g = blockIdx.x * blockDim.x + threadIdx.x; g < NGROUP; g += stride) {
        int hj4 = (g % (H_GRID / 4)) * 4;
        int t   = g / (H_GRID / 4);
        int wi  = t % W_GRID;
        int b   = t / W_GRID;

        float4 d4 = *reinterpret_cast<const float4*>(
            depth + ((size_t)b * W_GRID + wi) * H_GRID + hj4);
        const float* Mb = sM[b];
        float u = (float)hj4, v = (float)wi;

        float e0 = fmaf(u, Mb[0], fmaf(v, Mb[3], Mb[6]));
        float e1 = fmaf(u, Mb[1], fmaf(v, Mb[4], Mb[7]));
        float e2 = fmaf(u, Mb[2], fmaf(v, Mb[5], Mb[8]));
        float c0 = Mb[9], c1 = Mb[10], c2 = Mb[11];

        float dv[4] = {d4.x, d4.y, d4.z, d4.w};
        #pragma unroll
        for (int k = 0; k < 4; k++) {
            float q0 = fmaf(dv[k], e0, c0);
            float q1 = fmaf(dv[k], e1, c1);
            float q2 = fmaf(dv[k], e2, c2);
            float den = q2 + 1e-4f;
            // shared denominator: only the den-sign-selected extremum can win
            float qc = (den > 0.0f) ? fmaxf(q0, q1) : fminf(q0, q1);
            frac_max_update(qm, dm, qc, den);
            e0 += Mb[0]; e1 += Mb[1]; e2 += Mb[2];
        }
    }

    float local_max = __fdiv_rn(qm, dm);

    #pragma unroll
    for (int off = 16; off > 0; off >>= 1)
        local_max = fmaxf(local_max, __shfl_xor_sync(0xffffffffu, local_max, off));

    __shared__ float smax[8];
    int warp = threadIdx.x >> 5;
    int lane = threadIdx.x & 31;
    if (lane == 0) smax[warp] = local_max;
    __syncthreads();
    if (warp == 0) {
        float m = (lane < 8) ? smax[lane] : -INFINITY;
        #pragma unroll
        for (int off = 4; off > 0; off >>= 1)
            m = fmaxf(m, __shfl_xor_sync(0xffffffffu, m, off));
        if (lane == 0) atomicMax(&g_max_bits, float_to_ordered(m));
    }
}

// Pass 2: fast path for the dominant cell x,y ∈ [-1,0) (bit-identical to full
// path there), full bilinear otherwise. 4 px/thread.
__global__ void __launch_bounds__(256, 6) sample_kernel(
    const float* __restrict__ depth,
    const float* __restrict__ image,
    float* __restrict__ out)
{
    int g = blockIdx.x * blockDim.x + threadIdx.x;
    if (g < NGROUP) {
        int hj4 = (g % (H_GRID / 4)) * 4;
        int t   = g / (H_GRID / 4);
        int wi  = t % W_GRID;
        int b   = t / W_GRID;

        float gmax = ordered_to_float(g_max_bits);
        float rg = frcp_approx(gmax);
        float sx = (float)IMG_W * rg;
        float sy = (float)IMG_H * rg;

        float4 d4 = *reinterpret_cast<const float4*>(
            depth + ((size_t)b * W_GRID + wi) * H_GRID + hj4);
        const float* Mb = g_M[b];
        float u = (float)hj4, v = (float)wi;

        float m0 = Mb[0], m1 = Mb[1], m2 = Mb[2];
        float e0 = fmaf(u, m0, fmaf(v, Mb[3], Mb[6]));
        float e1 = fmaf(u, m1, fmaf(v, Mb[4], Mb[7]));
        float e2 = fmaf(u, m2, fmaf(v, Mb[5], Mb[8]));
        float c0 = Mb[9], c1 = Mb[10], c2 = Mb[11];

        const float* img_b = image + (size_t)b * 3 * IMG_H * IMG_W;
        // origin texels (L1-broadcast-hot) for the fast path
        float o0 = img_b[0];
        float o1 = img_b[IMG_H * IMG_W];
        float o2 = img_b[2 * IMG_H * IMG_W];

        float r[3][4];
        float dv[4] = {d4.x, d4.y, d4.z, d4.w};

        #pragma unroll
        for (int k = 0; k < 4; k++) {
            float q0 = fmaf(dv[k], e0, c0);
            float q1 = fmaf(dv[k], e1, c1);
            float q2 = fmaf(dv[k], e2, c2);
            e0 += m0; e1 += m1; e2 += m2;

            float rden = frcp_approx(q2 + 1e-4f);
            float x = fmaf(q0, rden * sx, -0.5f);
            float y = fmaf(q1, rden * sy, -0.5f);

            if (x >= -1.0f && x < 0.0f && y >= -1.0f && y < 0.0f) {
                // floor(x) = floor(y) = -1: only corner (0,0) is valid.
                // wx = x - (-1) = x + 1 (same FADD as slow path -> bit-identical)
                float wx = x + 1.0f;
                float wy = y + 1.0f;
                float w11 = wx * wy;
                r[0][k] = w11 * o0;
                r[1][k] = w11 * o1;
                r[2][k] = w11 * o2;
            } else {
                float x0f = floorf(x);
                float y0f = floorf(y);
                float wx = x - x0f;
                float wy = y - y0f;
                float x1f = x0f + 1.0f;
                float y1f = y0f + 1.0f;

                float vx0 = (x0f >= 0.0f && x0f <= (float)(IMG_W - 1)) ? 1.0f : 0.0f;
                float vx1 = (x1f >= 0.0f && x1f <= (float)(IMG_W - 1)) ? 1.0f : 0.0f;
                float vy0 = (y0f >= 0.0f && y0f <= (float)(IMG_H - 1)) ? 1.0f : 0.0f;
                float vy1 = (y1f >= 0.0f && y1f <= (float)(IMG_H - 1)) ? 1.0f : 0.0f;

                int xi0 = (int)fminf(fmaxf(x0f, 0.0f), (float)(IMG_W - 1));
                int xi1 = (int)fminf(fmaxf(x1f, 0.0f), (float)(IMG_W - 1));
                int yi0 = (int)fminf(fmaxf(y0f, 0.0f), (float)(IMG_H - 1));
                int yi1 = (int)fminf(fmaxf(y1f, 0.0f), (float)(IMG_H - 1));

                float wx0 = 1.0f - wx, wy0 = 1.0f - wy;
                float w00 = wx0 * wy0 * (vx0 * vy0);
                float w01 = wx  * wy0 * (vx1 * vy0);
                float w10 = wx0 * wy  * (vx0 * vy1);
                float w11 = wx  * wy  * (vx1 * vy1);

                int dx  = xi1 - xi0;
                int i00 = yi0 * IMG_W + xi0;
                int i01 = i00 + dx;
                int i10 = i00 + (yi1 - yi0) * IMG_W;
                int i11 = i10 + dx;

                #pragma unroll
                for (int c = 0; c < 3; c++) {
                    const float* ch = img_b + (size_t)c * (IMG_H * IMG_W);
                    r[c][k] = w00 * ch[i00] + w01 * ch[i01] + w10 * ch[i10] + w11 * ch[i11];
                }
            }
        }

        size_t out_base = ((size_t)b * 3) * (size_t)(W_GRID * H_GRID)
                        + (size_t)wi * H_GRID + hj4;
        #pragma unroll
        for (int c = 0; c < 3; c++) {
            float4 o = make_float4(r[c][0], r[c][1], r[c][2], r[c][3]);
            *reinterpret_cast<float4*>(out + out_base + (size_t)c * (W_GRID * H_GRID)) = o;
        }
    }

    // last-block cleanup: reset g_max_bits for the next graph replay.
    __syncthreads();
    if (threadIdx.x == 0) {
        __threadfence();
        unsigned int prev = atomicAdd(&g_done, 1u);
        if (prev == (unsigned)(P2_BLOCKS - 1)) {
            g_max_bits = 0u;
            g_done = 0u;
            __threadfence();
        }
    }
}

extern "C" void kernel_launch(void* const* d_in, const int* in_sizes, int n_in,
                              void* d_out, int out_size) {
    const float* depth = (const float*)d_in[0];   // [32, 640, 480, 1]
    const float* T     = (const float*)d_in[1];   // [32, 4, 4]
    const float* image = (const float*)d_in[2];   // [32, 3, 480, 640]
    const float* K     = (const float*)d_in[3];   // [3, 3]
    float* out = (float*)d_out;                   // [32, 3, 640, 480]

    uv_max_kernel<<<P1_BLOCKS, 256>>>(depth, T, K);
    sample_kernel<<<P2_BLOCKS, 256>>>(depth, image, out);
}

// round 15
// speedup vs baseline: 1.5467x; 1.0712x over previous
#include <cuda_runtime.h>
#include <math.h>

#define BATCH   32
#define W_GRID  640
#define H_GRID  480
#define IMG_H   480
#define IMG_W   640
#define NPIX    (BATCH * W_GRID * H_GRID)   // 9,830,400
#define NGROUP  (NPIX / 4)                  // 2,457,600 4-pixel groups
#define P1_BLOCKS 1200                      // 307200 threads -> exactly 8 groups/thread
#define P1_ITER   2                         // 2 iterations x 4-way batched loads
#define P2_BLOCKS ((NGROUP + 255) / 256)    // 9600

// zero-initialized; g_max_bits reset by sample_kernel's last block each run
__device__ unsigned int g_max_bits;
__device__ unsigned int g_done;
__device__ float g_M[BATCH][12];            // written by uv_max block 0

__device__ __forceinline__ unsigned int float_to_ordered(float f) {
    unsigned int u = __float_as_uint(f);
    return (u & 0x80000000u) ? ~u : (u | 0x80000000u);
}
__device__ __forceinline__ float ordered_to_float(unsigned int u) {
    unsigned int b = (u & 0x80000000u) ? (u ^ 0x80000000u) : ~u;
    return __uint_as_float(b);
}
__device__ __forceinline__ float frcp_approx(float x) {
    float r;
    asm("rcp.approx.f32 %0, %1;" : "=f"(r) : "f"(x));
    return r;
}

// Fraction-pair running max: current max is qm/dm. Candidate q/den wins iff
// (q*dm - qm*den) * (den*dm) > 0  — no division, no divergence.
__device__ __forceinline__ void frac_max_update(float& qm, float& dm, float q, float den) {
    float s   = den * dm;
    float cmp = fmaf(-qm, den, q * dm);
    if (cmp * s > 0.0f) { qm = q; dm = den; }
}

// Pass 1: build folded matrices per block; block 0 also publishes g_M for pass 2.
// Division-free global max, 4-way batched depth loads (MLP=4).
__global__ void __launch_bounds__(256, 5) uv_max_kernel(
    const float* __restrict__ depth,
    const float* __restrict__ T,
    const float* __restrict__ K)
{
    __shared__ float sM[BATCH][12];

    if (threadIdx.x < BATCH) {
        float a = K[0], b = K[1], c = K[2];
        float d = K[3], e = K[4], f = K[5];
        float g = K[6], h = K[7], i = K[8];
        float A  =  (e * i - f * h);
        float Bc = -(d * i - f * g);
        float C  =  (d * h - e * g);
        float det = a * A + b * Bc + c * C;
        float Ki[9];
        Ki[0] = __fdiv_rn(A, det);
        Ki[1] = __fdiv_rn(-(b * i - c * h), det);
        Ki[2] = __fdiv_rn((b * f - c * e), det);
        Ki[3] = __fdiv_rn(Bc, det);
        Ki[4] = __fdiv_rn((a * i - c * g), det);
        Ki[5] = __fdiv_rn(-(a * f - c * d), det);
        Ki[6] = __fdiv_rn(C, det);
        Ki[7] = __fdiv_rn(-(a * h - b * g), det);
        Ki[8] = __fdiv_rn((a * e - b * d), det);

        int bidx = threadIdx.x;
        const float* Tb = T + bidx * 16;
        float A2[9];
        #pragma unroll
        for (int k = 0; k < 3; k++)
            #pragma unroll
            for (int j = 0; j < 3; j++)
                A2[k * 3 + j] = fmaf(Tb[k * 4 + 0], K[0 * 3 + j],
                                fmaf(Tb[k * 4 + 1], K[1 * 3 + j],
                                     Tb[k * 4 + 2] * K[2 * 3 + j]));
        float Mv[12];
        #pragma unroll
        for (int r = 0; r < 3; r++)
            #pragma unroll
            for (int j = 0; j < 3; j++)
                Mv[r * 3 + j] = fmaf(Ki[r * 3 + 0], A2[0 * 3 + j],
                                fmaf(Ki[r * 3 + 1], A2[1 * 3 + j],
                                     Ki[r * 3 + 2] * A2[2 * 3 + j]));
        #pragma unroll
        for (int j = 0; j < 3; j++)
            Mv[9 + j] = fmaf(Tb[12], K[0 * 3 + j],
                        fmaf(Tb[13], K[1 * 3 + j],
                             Tb[14] * K[2 * 3 + j]));
        #pragma unroll
        for (int j = 0; j < 12; j++) sM[bidx][j] = Mv[j];
        if (blockIdx.x == 0) {
            #pragma unroll
            for (int j = 0; j < 12; j++) g_M[bidx][j] = Mv[j];
        }
    }
    __syncthreads();

    float qm = -1e30f, dm = 1.0f;

    const int tid = blockIdx.x * blockDim.x + threadIdx.x;
    const int stride = P1_BLOCKS * 256;           // 307200; NGROUP = 8*stride

    #pragma unroll
    for (int ii = 0; ii < P1_ITER; ii++) {
        // issue 4 independent coalesced float4 loads up front (MLP=4)
        float4 dd[4];
        int hj4s[4], wis[4], bs[4];
        #pragma unroll
        for (int j = 0; j < 4; j++) {
            int g  = tid + (ii * 4 + j) * stride;
            hj4s[j] = (g % (H_GRID / 4)) * 4;
            int t  = g / (H_GRID / 4);
            wis[j] = t % W_GRID;
            bs[j]  = t / W_GRID;
            dd[j] = *reinterpret_cast<const float4*>(
                depth + ((size_t)bs[j] * W_GRID + wis[j]) * H_GRID + hj4s[j]);
        }

        #pragma unroll
        for (int j = 0; j < 4; j++) {
            const float* Mb = sM[bs[j]];
            float u = (float)hj4s[j], v = (float)wis[j];

            float e0 = fmaf(u, Mb[0], fmaf(v, Mb[3], Mb[6]));
            float e1 = fmaf(u, Mb[1], fmaf(v, Mb[4], Mb[7]));
            float e2 = fmaf(u, Mb[2], fmaf(v, Mb[5], Mb[8]));
            float c0 = Mb[9], c1 = Mb[10], c2 = Mb[11];

            float dv[4] = {dd[j].x, dd[j].y, dd[j].z, dd[j].w};
            #pragma unroll
            for (int k = 0; k < 4; k++) {
                float q0 = fmaf(dv[k], e0, c0);
                float q1 = fmaf(dv[k], e1, c1);
                float q2 = fmaf(dv[k], e2, c2);
                float den = q2 + 1e-4f;
                float qc = (den > 0.0f) ? fmaxf(q0, q1) : fminf(q0, q1);
                frac_max_update(qm, dm, qc, den);
                e0 += Mb[0]; e1 += Mb[1]; e2 += Mb[2];
            }
        }
    }

    float local_max = __fdiv_rn(qm, dm);

    #pragma unroll
    for (int off = 16; off > 0; off >>= 1)
        local_max = fmaxf(local_max, __shfl_xor_sync(0xffffffffu, local_max, off));

    __shared__ float smax[8];
    int warp = threadIdx.x >> 5;
    int lane = threadIdx.x & 31;
    if (lane == 0) smax[warp] = local_max;
    __syncthreads();
    if (warp == 0) {
        float m = (lane < 8) ? smax[lane] : -INFINITY;
        #pragma unroll
        for (int off = 4; off > 0; off >>= 1)
            m = fmaxf(m, __shfl_xor_sync(0xffffffffu, m, off));
        if (lane == 0) atomicMax(&g_max_bits, float_to_ordered(m));
    }
}

// Pass 2: fast path for the dominant cell x,y ∈ [-1,0) (bit-identical to full
// path there), full bilinear otherwise. 4 px/thread.
__global__ void __launch_bounds__(256, 6) sample_kernel(
    const float* __restrict__ depth,
    const float* __restrict__ image,
    float* __restrict__ out)
{
    int g = blockIdx.x * blockDim.x + threadIdx.x;
    if (g < NGROUP) {
        int hj4 = (g % (H_GRID / 4)) * 4;
        int t   = g / (H_GRID / 4);
        int wi  = t % W_GRID;
        int b   = t / W_GRID;

        float gmax = ordered_to_float(g_max_bits);
        float rg = frcp_approx(gmax);
        float sx = (float)IMG_W * rg;
        float sy = (float)IMG_H * rg;

        float4 d4 = *reinterpret_cast<const float4*>(
            depth + ((size_t)b * W_GRID + wi) * H_GRID + hj4);
        const float* Mb = g_M[b];
        float u = (float)hj4, v = (float)wi;

        float m0 = Mb[0], m1 = Mb[1], m2 = Mb[2];
        float e0 = fmaf(u, m0, fmaf(v, Mb[3], Mb[6]));
        float e1 = fmaf(u, m1, fmaf(v, Mb[4], Mb[7]));
        float e2 = fmaf(u, m2, fmaf(v, Mb[5], Mb[8]));
        float c0 = Mb[9], c1 = Mb[10], c2 = Mb[11];

        const float* img_b = image + (size_t)b * 3 * IMG_H * IMG_W;
        float o0 = img_b[0];
        float o1 = img_b[IMG_H * IMG_W];
        float o2 = img_b[2 * IMG_H * IMG_W];

        float r[3][4];
        float dv[4] = {d4.x, d4.y, d4.z, d4.w};

        #pragma unroll
        for (int k = 0; k < 4; k++) {
            float q0 = fmaf(dv[k], e0, c0);
            float q1 = fmaf(dv[k], e1, c1);
            float q2 = fmaf(dv[k], e2, c2);
            e0 += m0; e1 += m1; e2 += m2;

            float rden = frcp_approx(q2 + 1e-4f);
            float x = fmaf(q0, rden * sx, -0.5f);
            float y = fmaf(q1, rden * sy, -0.5f);

            if (x >= -1.0f && x < 0.0f && y >= -1.0f && y < 0.0f) {
                float wx = x + 1.0f;
                float wy = y + 1.0f;
                float w11 = wx * wy;
                r[0][k] = w11 * o0;
                r[1][k] = w11 * o1;
                r[2][k] = w11 * o2;
            } else {
                float x0f = floorf(x);
                float y0f = floorf(y);
                float wx = x - x0f;
                float wy = y - y0f;
                float x1f = x0f + 1.0f;
                float y1f = y0f + 1.0f;

                float vx0 = (x0f >= 0.0f && x0f <= (float)(IMG_W - 1)) ? 1.0f : 0.0f;
                float vx1 = (x1f >= 0.0f && x1f <= (float)(IMG_W - 1)) ? 1.0f : 0.0f;
                float vy0 = (y0f >= 0.0f && y0f <= (float)(IMG_H - 1)) ? 1.0f : 0.0f;
                float vy1 = (y1f >= 0.0f && y1f <= (float)(IMG_H - 1)) ? 1.0f : 0.0f;

                int xi0 = (int)fminf(fmaxf(x0f, 0.0f), (float)(IMG_W - 1));
                int xi1 = (int)fminf(fmaxf(x1f, 0.0f), (float)(IMG_W - 1));
                int yi0 = (int)fminf(fmaxf(y0f, 0.0f), (float)(IMG_H - 1));
                int yi1 = (int)fminf(fmaxf(y1f, 0.0f), (float)(IMG_H - 1));

                float wx0 = 1.0f - wx, wy0 = 1.0f - wy;
                float w00 = wx0 * wy0 * (vx0 * vy0);
                float w01 = wx  * wy0 * (vx1 * vy0);
                float w10 = wx0 * wy  * (vx0 * vy1);
                float w11 = wx  * wy  * (vx1 * vy1);

                int dx  = xi1 - xi0;
                int i00 = yi0 * IMG_W + xi0;
                int i01 = i00 + dx;
                int i10 = i00 + (yi1 - yi0) * IMG_W;
                int i11 = i10 + dx;

                #pragma unroll
                for (int c = 0; c < 3; c++) {
                    const float* ch = img_b + (size_t)c * (IMG_H * IMG_W);
                    r[c][k] = w00 * ch[i00] + w01 * ch[i01] + w10 * ch[i10] + w11 * ch[i11];
                }
            }
        }

        size_t out_base = ((size_t)b * 3) * (size_t)(W_GRID * H_GRID)
                        + (size_t)wi * H_GRID + hj4;
        #pragma unroll
        for (int c = 0; c < 3; c++) {
            float4 o = make_float4(r[c][0], r[c][1], r[c][2], r[c][3]);
            *reinterpret_cast<float4*>(out + out_base + (size_t)c * (W_GRID * H_GRID)) = o;
        }
    }

    // last-block cleanup: reset g_max_bits for the next graph replay.
    __syncthreads();
    if (threadIdx.x == 0) {
        __threadfence();
        unsigned int prev = atomicAdd(&g_done, 1u);
        if (prev == (unsigned)(P2_BLOCKS - 1)) {
            g_max_bits = 0u;
            g_done = 0u;
            __threadfence();
        }
    }
}

extern "C" void kernel_launch(void* const* d_in, const int* in_sizes, int n_in,
                              void* d_out, int out_size) {
    const float* depth = (const float*)d_in[0];   // [32, 640, 480, 1]
    const float* T     = (const float*)d_in[1];   // [32, 4, 4]
    const float* image = (const float*)d_in[2];   // [32, 3, 480, 640]
    const float* K     = (const float*)d_in[3];   // [3, 3]
    float* out = (float*)d_out;                   // [32, 3, 640, 480]

    uv_max_kernel<<<P1_BLOCKS, 256>>>(depth, T, K);
    sample_kernel<<<P2_BLOCKS, 256>>>(depth, image, out);
}